// round 10
// baseline (speedup 1.0000x reference)
#include <cuda_runtime.h>

// LSTM2: 2-layer LSTM, B=1024, T=1024, H=64, input dim 1, output 1/step.
// Persistent-RNN: 128 CTAs x 512 threads, 8 batch rows per CTA.
// Thread = (unit n, k-eighth ke); lane = ke*4 + nl; n = wid*4 + nl.
// Each thread: all 4 gates of unit n x 8 rows x 8 k (f32x2 FMAs; weights in
// 32 regs per stage, amortized over all 8 rows -> weight LDS at its floor).
// 3-level select-butterfly over the 8 ke lanes -> lane ke holds row ke's four
// complete gate pre-activations; it owns that row's cell state (c1, c2).
// SMEM layouts (bank-exact):
//   weights: row pitch 68, plain order  -> LDS.128 at the 4-wavefront floor
//   h: float k at position k+4*(k>=32), row r at r*72+4*(r>=4)
//      -> h loads AND stores provably conflict-free (1 wavefront).

namespace {

constexpr int T_LEN = 1024;
constexpr int RPC   = 8;             // batch rows per CTA
constexpr int NTH   = 512;           // threads per CTA
constexpr int GRID  = 1024 / RPC;    // 128

constexpr int WP    = 68;            // weight row pitch (floats)
constexpr int HP    = 72;            // h row pitch (floats)
constexpr int HB    = 584;           // floats per h buffer (8 rows + stagger pad)

constexpr int SMEM_FLOATS = 3 * 256 * WP + 64 + 4 * HB + 16;
constexpr int SMEM_BYTES  = SMEM_FLOATS * 4;   // 218560 B

typedef unsigned long long u64;

__device__ __forceinline__ u64 fma2(u64 a, u64 b, u64 c) {
    u64 d;
    asm("fma.rn.f32x2 %0, %1, %2, %3;" : "=l"(d) : "l"(a), "l"(b), "l"(c));
    return d;
}
__device__ __forceinline__ float red2(u64 a) {
    return __uint_as_float((unsigned)a) + __uint_as_float((unsigned)(a >> 32));
}
__device__ __forceinline__ float tanh_f(float v) {
    float r;
    asm("tanh.approx.f32 %0, %1;" : "=f"(r) : "f"(v));
    return r;
}
__device__ __forceinline__ float sigm(float v) {
    return fmaf(tanh_f(0.5f * v), 0.5f, 0.5f);
}
__device__ __forceinline__ ulonglong2 ld2(const float* p) {
    return *(const ulonglong2*)p;
}
// h storage swizzle: float k -> k + 4*(k>=32); row r -> r*HP + 4*(r>=4)
__device__ __forceinline__ int hcol(int k) { return k + ((k >= 32) ? 4 : 0); }
__device__ __forceinline__ int hrow(int r) { return r * HP + ((r >= 4) ? 4 : 0); }

// One weight-matrix stage: pr[g][r] (+)= dot(w[g][kchunk], h[r][kchunk]).
// wb = weight base for unit n, this thread's k-chunk; gate rows at +64*WP.
// hb = h buffer base + this thread's k-chunk column offset.
template <bool ADD>
__device__ __forceinline__ void accum_stage(const float* __restrict__ wb,
                                            const float* __restrict__ hb,
                                            float (&pr)[4][8])
{
    ulonglong2 w[4][2];
    #pragma unroll
    for (int g = 0; g < 4; ++g) {
        w[g][0] = ld2(wb + g * 64 * WP);
        w[g][1] = ld2(wb + g * 64 * WP + 4);
    }
    #pragma unroll
    for (int r = 0; r < 8; ++r) {
        const float* hp = hb + hrow(r);
        ulonglong2 h0 = ld2(hp);
        ulonglong2 h1 = ld2(hp + 4);
        #pragma unroll
        for (int g = 0; g < 4; ++g) {
            u64 a = 0;
            a = fma2(w[g][0].x, h0.x, a);
            a = fma2(w[g][0].y, h0.y, a);
            a = fma2(w[g][1].x, h1.x, a);
            a = fma2(w[g][1].y, h1.y, a);
            if (ADD) pr[g][r] += red2(a); else pr[g][r] = red2(a);
        }
    }
}

// 3-level butterfly over ke lanes (lid bits 2,3,4): lane ke returns the
// fully-summed value for row ke. b0=ke&1, b1=(ke>>1)&1, b2=ke>>2.
__device__ __forceinline__ float bfly8(const float (&v)[8], int b0, int b1, int b2) {
    float w0 = (b0 ? v[1] : v[0]) + __shfl_xor_sync(~0u, b0 ? v[0] : v[1], 4);
    float w1 = (b0 ? v[3] : v[2]) + __shfl_xor_sync(~0u, b0 ? v[2] : v[3], 4);
    float w2 = (b0 ? v[5] : v[4]) + __shfl_xor_sync(~0u, b0 ? v[4] : v[5], 4);
    float w3 = (b0 ? v[7] : v[6]) + __shfl_xor_sync(~0u, b0 ? v[6] : v[7], 4);
    float u0 = (b1 ? w1 : w0) + __shfl_xor_sync(~0u, b1 ? w0 : w1, 8);
    float u1 = (b1 ? w3 : w2) + __shfl_xor_sync(~0u, b1 ? w2 : w3, 8);
    return (b2 ? u1 : u0) + __shfl_xor_sync(~0u, b2 ? u0 : u1, 16);
}

} // namespace

__global__ void __launch_bounds__(NTH, 1)
lstm2_kernel(const float* __restrict__ x,
             const float* __restrict__ w_ih1, const float* __restrict__ w_hh1,
             const float* __restrict__ b_ih1, const float* __restrict__ b_hh1,
             const float* __restrict__ w_ih2, const float* __restrict__ w_hh2,
             const float* __restrict__ b_ih2, const float* __restrict__ b_hh2,
             const float* __restrict__ w_lin, const float* __restrict__ b_lin,
             float* __restrict__ out)
{
    extern __shared__ float sm[];
    float* sWh1 = sm;                    // [256][68]
    float* sWi2 = sWh1 + 256 * WP;       // [256][68]
    float* sWh2 = sWi2 + 256 * WP;       // [256][68]
    float* sWl  = sWh2 + 256 * WP;       // [64]
    float* sH1  = sWl + 64;              // [2][HB]
    float* sH2  = sH1 + 2 * HB;          // [2][HB]
    float* sX   = sH2 + 2 * HB;          // [2][8]

    const int tid = threadIdx.x;
    const int rowbase = blockIdx.x * RPC;

    // ---- load weights into padded SMEM (plain k order, pitch 68) ----
    for (int i = tid; i < 256 * 64; i += NTH) {
        int j = i >> 6, k = i & 63;
        int off = j * WP + k;
        sWh1[off] = w_hh1[i];
        sWi2[off] = w_ih2[i];
        sWh2[off] = w_hh2[i];
    }
    if (tid < 64) sWl[tid] = w_lin[tid];
    for (int i = tid; i < 4 * HB; i += NTH) sH1[i] = 0.f;   // zeros h1 AND h2
    if (tid < RPC) sX[tid] = x[(rowbase + tid) * T_LEN];
    __syncthreads();

    // thread mapping: lane = ke*4 + nl; n = wid*4 + nl; this lane owns row ke
    const int lid = tid & 31;
    const int wid = tid >> 5;            // 0..15
    const int nl  = lid & 3;
    const int ke  = lid >> 2;            // k-eighth / owned row, 0..7
    const int n   = (wid << 2) | nl;     // 0..63
    const int b0 = ke & 1, b1 = (ke >> 1) & 1, b2 = ke >> 2;
    const int kcol = hcol(ke * 8);       // column offset of this k-chunk in h rows
    const int hst  = hrow(ke) + hcol(n); // store offset of (row ke, unit n)

    // per-thread constants from GMEM (once)
    const float bi1[4] = { b_ih1[n] + b_hh1[n],           b_ih1[n + 64] + b_hh1[n + 64],
                           b_ih1[n + 128] + b_hh1[n + 128], b_ih1[n + 192] + b_hh1[n + 192] };
    const float bi2[4] = { b_ih2[n] + b_hh2[n],           b_ih2[n + 64] + b_hh2[n + 64],
                           b_ih2[n + 128] + b_hh2[n + 128], b_ih2[n + 192] + b_hh2[n + 192] };
    const float wx[4]  = { w_ih1[n], w_ih1[n + 64], w_ih1[n + 128], w_ih1[n + 192] };
    const float blin = b_lin[0];

    // weight bases (unit n, this thread's 8-float k-chunk)
    const float* W1b = sWh1 + n * WP + ke * 8;
    const float* U2b = sWi2 + n * WP + ke * 8;
    const float* V2b = sWh2 + n * WP + ke * 8;

    // persistent cell state for row ke, unit n
    float c1 = 0.f, c2 = 0.f;

    for (int t = 0; t < T_LEN; ++t) {
        const int p = t & 1, q = p ^ 1;

        // prefetch next x (hidden under compute)
        float xn = 0.f;
        if (tid < RPC) {
            int tn = (t + 1 < T_LEN) ? (t + 1) : t;
            xn = x[(rowbase + tid) * T_LEN + tn];
        }

        // ============ layer 1 ============
        {
            float pr[4][8];
            accum_stage<false>(W1b, sH1 + p * HB + kcol, pr);
            float vi = bfly8(pr[0], b0, b1, b2);
            float vf = bfly8(pr[1], b0, b1, b2);
            float vg = bfly8(pr[2], b0, b1, b2);
            float vo = bfly8(pr[3], b0, b1, b2);
            const float xs = sX[p * RPC + ke];
            float ii = sigm(fmaf(wx[0], xs, bi1[0]) + vi);
            float ff = sigm(fmaf(wx[1], xs, bi1[1]) + vf);
            float gc = tanh_f(fmaf(wx[2], xs, bi1[2]) + vg);
            float oo = sigm(fmaf(wx[3], xs, bi1[3]) + vo);
            c1 = ff * c1 + ii * gc;
            sH1[q * HB + hst] = oo * tanh_f(c1);
        }
        if (tid < RPC) sX[q * RPC + tid] = xn;
        __syncthreads();   // h1[q] + x[q] published

        // ============ layer 2: U*h1[q] + V*h2[p] ============
        {
            float pr[4][8];
            accum_stage<false>(U2b, sH1 + q * HB + kcol, pr);
            accum_stage<true >(V2b, sH2 + p * HB + kcol, pr);
            float vi = bfly8(pr[0], b0, b1, b2);
            float vf = bfly8(pr[1], b0, b1, b2);
            float vg = bfly8(pr[2], b0, b1, b2);
            float vo = bfly8(pr[3], b0, b1, b2);
            float ii = sigm(bi2[0] + vi);
            float ff = sigm(bi2[1] + vf);
            float gc = tanh_f(bi2[2] + vg);
            float oo = sigm(bi2[3] + vo);
            c2 = ff * c2 + ii * gc;
            sH2[q * HB + hst] = oo * tanh_f(c2);
        }
        __syncthreads();   // h2[q] published

        // ====== output: warp w (w<8) reduces row w of h2[q] against w_lin ======
        if (wid < RPC) {
            const float* hr = sH2 + q * HB + hrow(wid);
            float v = hr[lid] * sWl[lid] + hr[lid + 36] * sWl[lid + 32];
            #pragma unroll
            for (int off = 16; off; off >>= 1)
                v += __shfl_xor_sync(0xffffffffu, v, off);
            if (lid == 0) out[(rowbase + wid) * T_LEN + t] = v + blin;
        }
    }
}

extern "C" void kernel_launch(void* const* d_in, const int* in_sizes, int n_in,
                              void* d_out, int out_size)
{
    const float* x     = (const float*)d_in[0];
    const float* w_ih1 = (const float*)d_in[1];
    const float* w_hh1 = (const float*)d_in[2];
    const float* b_ih1 = (const float*)d_in[3];
    const float* b_hh1 = (const float*)d_in[4];
    const float* w_ih2 = (const float*)d_in[5];
    const float* w_hh2 = (const float*)d_in[6];
    const float* b_ih2 = (const float*)d_in[7];
    const float* b_hh2 = (const float*)d_in[8];
    const float* w_lin = (const float*)d_in[9];
    const float* b_lin = (const float*)d_in[10];

    cudaFuncSetAttribute(lstm2_kernel,
                         cudaFuncAttributeMaxDynamicSharedMemorySize, SMEM_BYTES);

    lstm2_kernel<<<GRID, NTH, SMEM_BYTES>>>(
        x, w_ih1, w_hh1, b_ih1, b_hh1,
        w_ih2, w_hh2, b_ih2, b_hh2,
        w_lin, b_lin, (float*)d_out);
}